// round 2
// baseline (speedup 1.0000x reference)
#include <cuda_runtime.h>
#include <math.h>

// Problem constants (fixed shapes)
#define B_  8
#define N_  4096
#define C_  256
#define K_  4
#define NK_ (N_ * K_)

#define BM 64
#define BN 128
#define BK 32
#define THREADS 256

// Normalized features scratch (32 MB) — allocation-free rule: __device__ global.
__device__ float g_fn[(size_t)B_ * N_ * C_];

// ---------------------------------------------------------------------------
// Kernel 1: row-wise L2 normalize. One warp per row (256 floats).
// ---------------------------------------------------------------------------
__global__ void normalize_kernel(const float* __restrict__ x) {
    int row  = blockIdx.x * 8 + (threadIdx.x >> 5);
    int lane = threadIdx.x & 31;
    const float4* r = (const float4*)(x + (size_t)row * C_);
    float4 v0 = r[lane];
    float4 v1 = r[lane + 32];
    float s = v0.x * v0.x + v0.y * v0.y + v0.z * v0.z + v0.w * v0.w
            + v1.x * v1.x + v1.y * v1.y + v1.z * v1.z + v1.w * v1.w;
#pragma unroll
    for (int off = 16; off; off >>= 1)
        s += __shfl_xor_sync(0xffffffffu, s, off);
    float nrm = sqrtf(s);
    float4* o = (float4*)(g_fn + (size_t)row * C_);
    float4 a, b;
    a.x = v0.x / nrm; a.y = v0.y / nrm; a.z = v0.z / nrm; a.w = v0.w / nrm;
    b.x = v1.x / nrm; b.y = v1.y / nrm; b.z = v1.z / nrm; b.w = v1.w / nrm;
    o[lane]      = a;
    o[lane + 32] = b;
}

// ---------------------------------------------------------------------------
// Kernel 2: fused sim-GEMM + running top-4 + edge emit.
// CTA: 64 rows x all 4096 cols of one batch.
// Threads 256 as 16x16; microtile 4 rows x 8 cols.
// Warp = two half-warps (ty = 2w, 2w+1); each half owns 4 rows -> shfl merge.
// ---------------------------------------------------------------------------
__global__ __launch_bounds__(THREADS, 2)
void knn_kernel(float* __restrict__ out) {
    const int b    = blockIdx.y;
    const int row0 = blockIdx.x * BM;
    const float* __restrict__ fb = g_fn + (size_t)b * N_ * C_;

    __shared__ __align__(16) float As[BM][BK + 4];   // 64 x 36
    __shared__ __align__(16) float Bs[BK][BN + 4];   // 32 x 132

    const int tid = threadIdx.x;
    const int ty  = tid >> 4;       // 0..15 (thread-row)
    const int tx  = tid & 15;       // 0..15 (thread-col)

    float topv[4][4];
    int   topi[4][4];
#pragma unroll
    for (int i = 0; i < 4; i++)
#pragma unroll
        for (int s = 0; s < 4; s++) { topv[i][s] = -INFINITY; topi[i][s] = 0x7fffffff; }

    for (int ct = 0; ct < N_ / BN; ct++) {
        const int col0 = ct * BN;
        float acc[4][8];
#pragma unroll
        for (int i = 0; i < 4; i++)
#pragma unroll
            for (int j = 0; j < 8; j++) acc[i][j] = 0.0f;

        for (int kk = 0; kk < C_; kk += BK) {
            __syncthreads();   // previous chunk's readers done
            // Load A chunk: 64 rows x 32 k  (512 float4, 2 per thread)
#pragma unroll
            for (int it = 0; it < 2; it++) {
                int lin = it * THREADS + tid;
                int m = lin >> 3, q = lin & 7;
                float4 v = *(const float4*)(fb + (size_t)(row0 + m) * C_ + kk + 4 * q);
                *(float4*)&As[m][4 * q] = v;
            }
            // Load B chunk transposed: 128 cols x 32 k (1024 float4, 4 per thread)
#pragma unroll
            for (int it = 0; it < 4; it++) {
                int lin = it * THREADS + tid;
                int n = lin >> 3, q = lin & 7;
                float4 v = *(const float4*)(fb + (size_t)(col0 + n) * C_ + kk + 4 * q);
                Bs[4 * q + 0][n] = v.x;
                Bs[4 * q + 1][n] = v.y;
                Bs[4 * q + 2][n] = v.z;
                Bs[4 * q + 3][n] = v.w;
            }
            __syncthreads();
#pragma unroll
            for (int k = 0; k < BK; k++) {
                float4 b0 = *(const float4*)&Bs[k][tx * 8];
                float4 b1 = *(const float4*)&Bs[k][tx * 8 + 4];
#pragma unroll
                for (int i = 0; i < 4; i++) {
                    float a = As[ty * 4 + i][k];
                    acc[i][0] += a * b0.x;
                    acc[i][1] += a * b0.y;
                    acc[i][2] += a * b0.z;
                    acc[i][3] += a * b0.w;
                    acc[i][4] += a * b1.x;
                    acc[i][5] += a * b1.y;
                    acc[i][6] += a * b1.z;
                    acc[i][7] += a * b1.w;
                }
            }
        }

        // Fold this 4x8 result block into per-lane sorted top-4 lists.
#pragma unroll
        for (int i = 0; i < 4; i++) {
            const int g = row0 + ty * 4 + i;
#pragma unroll
            for (int j = 0; j < 8; j++) {
                int   c = col0 + tx * 8 + j;
                float v = acc[i][j];
                if (c != g && v > topv[i][3]) {
                    if (v > topv[i][0]) {
                        topv[i][3] = topv[i][2]; topi[i][3] = topi[i][2];
                        topv[i][2] = topv[i][1]; topi[i][2] = topi[i][1];
                        topv[i][1] = topv[i][0]; topi[i][1] = topi[i][0];
                        topv[i][0] = v;          topi[i][0] = c;
                    } else if (v > topv[i][1]) {
                        topv[i][3] = topv[i][2]; topi[i][3] = topi[i][2];
                        topv[i][2] = topv[i][1]; topi[i][2] = topi[i][1];
                        topv[i][1] = v;          topi[i][1] = c;
                    } else if (v > topv[i][2]) {
                        topv[i][3] = topv[i][2]; topi[i][3] = topi[i][2];
                        topv[i][2] = v;          topi[i][2] = c;
                    } else {
                        topv[i][3] = v;          topi[i][3] = c;
                    }
                }
            }
        }
    }

    // Merge the 16 lanes of each half-warp (shfl_xor offsets < 16 stay in-half),
    // then emit edges. Output layout (float32):
    //   [b*2*NK .. ]        : src indices
    //   [b*2*NK + NK .. ]   : tgt indices
    //   [B*2*NK + b*NK .. ] : weights
    const int lh = tid & 15;  // lane within half-warp == tx
    const size_t ibase = (size_t)b * 2 * NK_;
    const size_t wbase = (size_t)B_ * 2 * NK_ + (size_t)b * NK_;
#pragma unroll
    for (int i = 0; i < 4; i++) {
        const int g = row0 + ty * 4 + i;
        int p = 0;
#pragma unroll
        for (int s = 0; s < 4; s++) {
            float cv = (p < 4) ? topv[i][p] : -INFINITY;
            int   ci = (p < 4) ? topi[i][p] : 0x7fffffff;
#pragma unroll
            for (int off = 8; off; off >>= 1) {
                float ov = __shfl_xor_sync(0xffffffffu, cv, off);
                int   oi = __shfl_xor_sync(0xffffffffu, ci, off);
                if (ov > cv || (ov == cv && oi < ci)) { cv = ov; ci = oi; }
            }
            if (p < 4 && topi[i][p] == ci) p++;   // winner lane pops its list
            if (lh == s) {
                out[ibase + (size_t)g * K_ + s]       = (float)g;
                out[ibase + NK_ + (size_t)g * K_ + s] = (float)ci;
                out[wbase + (size_t)g * K_ + s]       = cv;
            }
        }
    }
}

// ---------------------------------------------------------------------------
extern "C" void kernel_launch(void* const* d_in, const int* in_sizes, int n_in,
                              void* d_out, int out_size) {
    (void)in_sizes; (void)n_in; (void)out_size;
    const float* x = (const float*)d_in[0];
    float* out = (float*)d_out;

    normalize_kernel<<<(B_ * N_) / 8, 256>>>(x);
    dim3 grid(N_ / BM, B_);
    knn_kernel<<<grid, THREADS>>>(out);
}